// round 4
// baseline (speedup 1.0000x reference)
#include <cuda_runtime.h>
#include <cstdint>

// Problem constants
#define E           30                 // channels per cell (B*5 + C)
#define CELLS       802816             // 16384 * 7 * 7
#define CPB         128                // cells per tile
#define THREADS     128
#define TILE_FLOATS (CPB * E)          // 3840
#define TILE_BYTES  (TILE_FLOATS * 4)  // 15360 per tensor
#define STAGE_FLOATS (2 * TILE_FLOATS) // pred + tgt
#define STAGE_BYTES  (2 * TILE_BYTES)  // 30720
#define STAGES      3
#define NTILES      (CELLS / CPB)      // 6272
#define NBLK        304                // 2 blocks/SM on 152 SMs, one wave
#define SMEM_DYN    (STAGES * STAGE_BYTES)  // 92160

__device__ __forceinline__ uint32_t smem_u32(const void* p) {
    uint32_t a;
    asm("{ .reg .u64 t; cvta.to.shared.u64 t, %1; cvt.u32.u64 %0, t; }"
        : "=r"(a) : "l"(p));
    return a;
}

__device__ __forceinline__ void issue_tile(uint32_t sp_a, uint32_t st_a,
                                           uint32_t mbar_a,
                                           const float* pred_src,
                                           const float* tgt_src) {
    asm volatile("mbarrier.arrive.expect_tx.shared.b64 _, [%0], %1;"
                 :: "r"(mbar_a), "r"(STAGE_BYTES) : "memory");
    asm volatile(
        "cp.async.bulk.shared::cta.global.mbarrier::complete_tx::bytes "
        "[%0], [%1], %2, [%3];"
        :: "r"(sp_a), "l"(pred_src), "r"(TILE_BYTES), "r"(mbar_a) : "memory");
    asm volatile(
        "cp.async.bulk.shared::cta.global.mbarrier::complete_tx::bytes "
        "[%0], [%1], %2, [%3];"
        :: "r"(st_a), "l"(tgt_src), "r"(TILE_BYTES), "r"(mbar_a) : "memory");
}

__device__ __forceinline__ void wait_parity(uint32_t mbar_a, uint32_t parity) {
    uint32_t done;
    asm volatile(
        "{\n\t"
        ".reg .pred p;\n\t"
        "mbarrier.try_wait.parity.acquire.cta.shared::cta.b64 p, [%1], %2;\n\t"
        "selp.b32 %0, 1, 0, p;\n\t"
        "}"
        : "=r"(done) : "r"(mbar_a), "r"(parity) : "memory");
    if (!done) {
        asm volatile(
            "{\n\t"
            ".reg .pred P1;\n\t"
            "WAIT_LOOP_%=:\n\t"
            "mbarrier.try_wait.parity.acquire.cta.shared::cta.b64 P1, [%0], %1, 0x989680;\n\t"
            "@P1 bra.uni WAIT_DONE_%=;\n\t"
            "bra.uni WAIT_LOOP_%=;\n\t"
            "WAIT_DONE_%=:\n\t"
            "}"
            :: "r"(mbar_a), "r"(parity) : "memory");
    }
}

__global__ __launch_bounds__(THREADS)
void yolo_loss_kernel(const float* __restrict__ pred,
                      const float* __restrict__ tgt,
                      float* __restrict__ out) {
    extern __shared__ __align__(16) float smem[];  // STAGES * STAGE_FLOATS
    __shared__ __align__(8) uint64_t full[STAGES];
    __shared__ float red[THREADS / 32][5];

    const int tid = threadIdx.x;

    uint32_t mbar_a[STAGES];
    uint32_t sp_a[STAGES], st_a[STAGES];
    #pragma unroll
    for (int s = 0; s < STAGES; s++) {
        mbar_a[s] = smem_u32(&full[s]);
        sp_a[s] = smem_u32(smem + s * STAGE_FLOATS);
        st_a[s] = smem_u32(smem + s * STAGE_FLOATS + TILE_FLOATS);
    }

    if (tid == 0) {
        #pragma unroll
        for (int s = 0; s < STAGES; s++)
            asm volatile("mbarrier.init.shared.b64 [%0], %1;"
                         :: "r"(mbar_a[s]), "r"(1) : "memory");
    }
    __syncthreads();

    // Tiles assigned to this block (grid-stride).
    const int bid = blockIdx.x;

    // Prologue: fill the pipeline.
    if (tid == 0) {
        int s = 0;
        for (int t = bid; t < NTILES && s < STAGES; t += NBLK, s++) {
            const long long base = (long long)t * TILE_FLOATS;
            issue_tile(sp_a[s], st_a[s], mbar_a[s], pred + base, tgt + base);
        }
    }

    float axy = 0.f, awh = 0.f, aobj = 0.f, anoobj = 0.f, acls = 0.f;

    int i = 0;  // iteration index within this block
    for (int t = bid; t < NTILES; t += NBLK, i++) {
        const int s = i % STAGES;
        const uint32_t parity = (i / STAGES) & 1u;

        wait_parity(mbar_a[s], parity);

        // ---- Per-thread cell compute (all 128 threads active) ----
        const float* p = smem + s * STAGE_FLOATS + tid * E;
        const float* g = smem + s * STAGE_FLOATS + TILE_FLOATS + tid * E;

        const float conf = g[4];
        const float m  = (conf > 0.0f)  ? 1.0f : 0.0f;
        const float nm = (conf == 0.0f) ? 1.0f : 0.0f;

        const float t0x = g[0], t0y = g[1], t0X = g[2], t0Y = g[3];
        const float a2 = (t0X - t0x) * (t0Y - t0y);

        float iou[2];
        #pragma unroll
        for (int b = 0; b < 2; b++) {
            const float* pb = p + b * 5;
            float ltx = fmaxf(pb[0], t0x);
            float lty = fmaxf(pb[1], t0y);
            float rbx = fminf(pb[2], t0X);
            float rby = fminf(pb[3], t0Y);
            float w = fmaxf(rbx - ltx, 0.0f);
            float h = fmaxf(rby - lty, 0.0f);
            float inter = w * h;
            float a1 = (pb[2] - pb[0]) * (pb[3] - pb[1]);
            iou[b] = inter / (a1 + a2 - inter);
        }

        // jnp.argmax takes the FIRST max on ties -> strict '>' for box 1
        const int best = (iou[1] > iou[0]) ? 1 : 0;
        const float maxiou = iou[best];

        const float* pb = p + best * 5;
        const float* tb = g + best * 5;

        const float dx = pb[0] - tb[0];
        const float dy = pb[1] - tb[1];
        axy += m * (dx * dx + dy * dy);

        const float dw = sqrtf(pb[2]) - sqrtf(tb[2]);
        const float dh = sqrtf(pb[3]) - sqrtf(tb[3]);
        awh += m * (dw * dw + dh * dh);

        const float dobj = pb[4] - maxiou;
        aobj += m * dobj * dobj;

        const float d4 = p[4] - g[4];
        const float d9 = p[9] - g[9];
        anoobj += nm * (d4 * d4 + d9 * d9);

        float cs = 0.0f;
        #pragma unroll
        for (int c = 10; c < 30; c++) {
            const float d = p[c] - g[c];
            cs += d * d;
        }
        acls += m * cs;

        // All threads done reading stage s -> safe to re-arm it.
        __syncthreads();

        const int tnext = t + STAGES * NBLK;
        if (tid == 0 && tnext < NTILES) {
            const long long base = (long long)tnext * TILE_FLOATS;
            issue_tile(sp_a[s], st_a[s], mbar_a[s], pred + base, tgt + base);
        }
    }

    // ---- Block reduction of 5 accumulated partials ----
    #pragma unroll
    for (int o = 16; o > 0; o >>= 1) {
        axy    += __shfl_down_sync(0xffffffffu, axy,    o);
        awh    += __shfl_down_sync(0xffffffffu, awh,    o);
        aobj   += __shfl_down_sync(0xffffffffu, aobj,   o);
        anoobj += __shfl_down_sync(0xffffffffu, anoobj, o);
        acls   += __shfl_down_sync(0xffffffffu, acls,   o);
    }
    const int wid  = tid >> 5;
    const int lane = tid & 31;
    if (lane == 0) {
        red[wid][0] = axy;
        red[wid][1] = awh;
        red[wid][2] = aobj;
        red[wid][3] = anoobj;
        red[wid][4] = acls;
    }
    __syncthreads();
    if (tid < 5) {
        float s = 0.0f;
        #pragma unroll
        for (int w = 0; w < THREADS / 32; w++) s += red[w][tid];
        atomicAdd(out + tid, s);
    }
}

extern "C" void kernel_launch(void* const* d_in, const int* in_sizes, int n_in,
                              void* d_out, int out_size) {
    const float* pred = (const float*)d_in[0];
    const float* tgt  = (const float*)d_in[1];
    float* out = (float*)d_out;

    cudaFuncSetAttribute(yolo_loss_kernel,
                         cudaFuncAttributeMaxDynamicSharedMemorySize, SMEM_DYN);
    cudaMemsetAsync(out, 0, (size_t)out_size * sizeof(float));
    yolo_loss_kernel<<<NBLK, THREADS, SMEM_DYN>>>(pred, tgt, out);
}

// round 9
// speedup vs baseline: 1.0390x; 1.0390x over previous
#include <cuda_runtime.h>
#include <cstdint>

// Problem constants
#define E           30                 // channels per cell (B*5 + C)
#define CELLS       802816             // 16384 * 7 * 7
#define CPB         128                // cells per block
#define THREADS     128
#define TILE_FLOATS (CPB * E)          // 3840
#define TILE_BYTES  (TILE_FLOATS * 4)  // 15360 per tensor
#define NTILES      (CELLS / CPB)      // 6272
#define PF_AHEAD    1064               // ~one wave (152 SMs * 7 blocks) ahead

__device__ __forceinline__ uint32_t smem_u32(const void* p) {
    uint32_t a;
    asm("{ .reg .u64 t; cvta.to.shared.u64 t, %1; cvt.u32.u64 %0, t; }"
        : "=r"(a) : "l"(p));
    return a;
}

__global__ __launch_bounds__(THREADS)
void yolo_loss_kernel(const float* __restrict__ pred,
                      const float* __restrict__ tgt,
                      float* __restrict__ out) {
    __shared__ __align__(16) float sp[TILE_FLOATS];
    __shared__ __align__(16) float st[TILE_FLOATS];
    __shared__ __align__(8)  uint64_t mbar;
    __shared__ float red[THREADS / 32][5];

    const int tid = threadIdx.x;
    const long long base = (long long)blockIdx.x * TILE_FLOATS;

    // ---- Warp 1, immediately: prefetch the tile one wave ahead into L2.
    // No dependencies -> DRAM read stream stays continuously queued,
    // independent of this block's mbarrier/compute lifecycle.
    if (tid == 32) {
        const long long tpf = (long long)blockIdx.x + PF_AHEAD;
        if (tpf < NTILES) {
            const long long pfbase = tpf * TILE_FLOATS;
            asm volatile("cp.async.bulk.prefetch.L2.global [%0], %1;"
                         :: "l"(pred + pfbase), "r"(TILE_BYTES) : "memory");
            asm volatile("cp.async.bulk.prefetch.L2.global [%0], %1;"
                         :: "l"(tgt + pfbase), "r"(TILE_BYTES) : "memory");
        }
    }

    const uint32_t mbar_a = smem_u32(&mbar);

    if (tid == 0) {
        asm volatile("mbarrier.init.shared.b64 [%0], %1;"
                     :: "r"(mbar_a), "r"(1) : "memory");
    }
    __syncthreads();

    if (tid == 0) {
        asm volatile("mbarrier.arrive.expect_tx.shared.b64 _, [%0], %1;"
                     :: "r"(mbar_a), "r"(2 * TILE_BYTES) : "memory");
        asm volatile(
            "cp.async.bulk.shared::cta.global.mbarrier::complete_tx::bytes "
            "[%0], [%1], %2, [%3];"
            :: "r"(smem_u32(sp)), "l"(pred + base), "r"(TILE_BYTES), "r"(mbar_a)
            : "memory");
        asm volatile(
            "cp.async.bulk.shared::cta.global.mbarrier::complete_tx::bytes "
            "[%0], [%1], %2, [%3];"
            :: "r"(smem_u32(st)), "l"(tgt + base), "r"(TILE_BYTES), "r"(mbar_a)
            : "memory");
    }

    // Wait for both TMA copies (phase parity 0).
    {
        uint32_t done;
        asm volatile(
            "{\n\t"
            ".reg .pred p;\n\t"
            "mbarrier.try_wait.parity.acquire.cta.shared::cta.b64 p, [%1], %2;\n\t"
            "selp.b32 %0, 1, 0, p;\n\t"
            "}"
            : "=r"(done) : "r"(mbar_a), "r"(0) : "memory");
        if (!done) {
            asm volatile(
                "{\n\t"
                ".reg .pred P1;\n\t"
                "WAIT_LOOP_%=:\n\t"
                "mbarrier.try_wait.parity.acquire.cta.shared::cta.b64 P1, [%0], %1, 0x989680;\n\t"
                "@P1 bra.uni WAIT_DONE_%=;\n\t"
                "bra.uni WAIT_LOOP_%=;\n\t"
                "WAIT_DONE_%=:\n\t"
                "}"
                :: "r"(mbar_a), "r"(0) : "memory");
        }
    }

    // ---- Per-thread cell compute (all 128 threads active) ----
    const float* p = sp + tid * E;
    const float* g = st + tid * E;

    const float conf = g[4];
    const float m  = (conf > 0.0f)  ? 1.0f : 0.0f;
    const float nm = (conf == 0.0f) ? 1.0f : 0.0f;

    const float t0x = g[0], t0y = g[1], t0X = g[2], t0Y = g[3];
    const float a2 = (t0X - t0x) * (t0Y - t0y);

    float iou[2];
    #pragma unroll
    for (int b = 0; b < 2; b++) {
        const float* pb = p + b * 5;
        float ltx = fmaxf(pb[0], t0x);
        float lty = fmaxf(pb[1], t0y);
        float rbx = fminf(pb[2], t0X);
        float rby = fminf(pb[3], t0Y);
        float w = fmaxf(rbx - ltx, 0.0f);
        float h = fmaxf(rby - lty, 0.0f);
        float inter = w * h;
        float a1 = (pb[2] - pb[0]) * (pb[3] - pb[1]);
        iou[b] = inter / (a1 + a2 - inter);
    }

    // jnp.argmax takes the FIRST max on ties -> strict '>' for box 1
    const int best = (iou[1] > iou[0]) ? 1 : 0;
    const float maxiou = iou[best];

    const float* pb = p + best * 5;
    const float* tb = g + best * 5;

    const float dx = pb[0] - tb[0];
    const float dy = pb[1] - tb[1];
    float lxy = m * (dx * dx + dy * dy);

    const float dw = sqrtf(pb[2]) - sqrtf(tb[2]);
    const float dh = sqrtf(pb[3]) - sqrtf(tb[3]);
    float lwh = m * (dw * dw + dh * dh);

    const float dobj = pb[4] - maxiou;
    float lobj = m * dobj * dobj;

    const float d4 = p[4] - g[4];
    const float d9 = p[9] - g[9];
    float lnoobj = nm * (d4 * d4 + d9 * d9);

    float cs = 0.0f;
    #pragma unroll
    for (int c = 10; c < 30; c++) {
        const float d = p[c] - g[c];
        cs += d * d;
    }
    float lcls = m * cs;

    // ---- Block reduction of 5 partials ----
    #pragma unroll
    for (int o = 16; o > 0; o >>= 1) {
        lxy    += __shfl_down_sync(0xffffffffu, lxy,    o);
        lwh    += __shfl_down_sync(0xffffffffu, lwh,    o);
        lobj   += __shfl_down_sync(0xffffffffu, lobj,   o);
        lnoobj += __shfl_down_sync(0xffffffffu, lnoobj, o);
        lcls   += __shfl_down_sync(0xffffffffu, lcls,   o);
    }
    const int wid  = tid >> 5;
    const int lane = tid & 31;
    if (lane == 0) {
        red[wid][0] = lxy;
        red[wid][1] = lwh;
        red[wid][2] = lobj;
        red[wid][3] = lnoobj;
        red[wid][4] = lcls;
    }
    __syncthreads();
    if (tid < 5) {
        float s = 0.0f;
        #pragma unroll
        for (int w = 0; w < THREADS / 32; w++) s += red[w][tid];
        atomicAdd(out + tid, s);
    }
}

extern "C" void kernel_launch(void* const* d_in, const int* in_sizes, int n_in,
                              void* d_out, int out_size) {
    const float* pred = (const float*)d_in[0];
    const float* tgt  = (const float*)d_in[1];
    float* out = (float*)d_out;

    cudaMemsetAsync(out, 0, (size_t)out_size * sizeof(float));
    yolo_loss_kernel<<<NTILES, THREADS>>>(pred, tgt, out);
}

// round 11
// speedup vs baseline: 1.0981x; 1.0568x over previous
#include <cuda_runtime.h>
#include <cstdint>

// Problem constants
#define E           30                  // channels per cell (B*5 + C)
#define CELLS       802816              // 16384 * 7 * 7
#define CPB         112                 // cells per tile
#define THREADS     128
#define TILE_FLOATS (CPB * E)           // 3360
#define TILE_BYTES  (TILE_FLOATS * 4)   // 13440 per tensor
#define STAGE_FLOATS (2 * TILE_FLOATS)  // pred + tgt
#define STAGE_BYTES  (2 * TILE_BYTES)   // 26880
#define NBLK        3584                // CELLS / (2*CPB)
#define SMEM_DYN    (2 * STAGE_BYTES)   // 53760: two buffered tiles

__device__ __forceinline__ uint32_t smem_u32(const void* p) {
    uint32_t a;
    asm("{ .reg .u64 t; cvta.to.shared.u64 t, %1; cvt.u32.u64 %0, t; }"
        : "=r"(a) : "l"(p));
    return a;
}

__device__ __forceinline__ void wait_parity0(uint32_t mbar_a) {
    uint32_t done;
    asm volatile(
        "{\n\t"
        ".reg .pred p;\n\t"
        "mbarrier.try_wait.parity.acquire.cta.shared::cta.b64 p, [%1], 0;\n\t"
        "selp.b32 %0, 1, 0, p;\n\t"
        "}"
        : "=r"(done) : "r"(mbar_a) : "memory");
    if (!done) {
        asm volatile(
            "{\n\t"
            ".reg .pred P1;\n\t"
            "WAIT_LOOP_%=:\n\t"
            "mbarrier.try_wait.parity.acquire.cta.shared::cta.b64 P1, [%0], 0, 0x989680;\n\t"
            "@P1 bra.uni WAIT_DONE_%=;\n\t"
            "bra.uni WAIT_LOOP_%=;\n\t"
            "WAIT_DONE_%=:\n\t"
            "}"
            :: "r"(mbar_a) : "memory");
    }
}

__global__ __launch_bounds__(THREADS)
void yolo_loss_kernel(const float* __restrict__ pred,
                      const float* __restrict__ tgt,
                      float* __restrict__ out) {
    extern __shared__ __align__(16) float smem[];  // 2 * STAGE_FLOATS
    __shared__ __align__(8) uint64_t mbar[2];
    __shared__ float red[THREADS / 32][5];

    const int tid = threadIdx.x;

    // Buffer k holds tile (2*bid + k): [pred | tgt] each TILE_FLOATS.
    uint32_t mbar_a[2], sp_a[2], st_a[2];
    #pragma unroll
    for (int k = 0; k < 2; k++) {
        mbar_a[k] = smem_u32(&mbar[k]);
        sp_a[k] = smem_u32(smem + k * STAGE_FLOATS);
        st_a[k] = smem_u32(smem + k * STAGE_FLOATS + TILE_FLOATS);
    }

    // tid 0 inits both mbarriers AND issues all four TMA copies immediately.
    // Other threads only touch the barriers after the __syncthreads below,
    // so the init->use race is confined to tid 0's own program order.
    if (tid == 0) {
        #pragma unroll
        for (int k = 0; k < 2; k++) {
            asm volatile("mbarrier.init.shared.b64 [%0], 1;"
                         :: "r"(mbar_a[k]) : "memory");
        }
        asm volatile("fence.proxy.async.shared::cta;" ::: "memory");
        #pragma unroll
        for (int k = 0; k < 2; k++) {
            const long long base = ((long long)blockIdx.x * 2 + k) * TILE_FLOATS;
            asm volatile("mbarrier.arrive.expect_tx.shared.b64 _, [%0], %1;"
                         :: "r"(mbar_a[k]), "r"(STAGE_BYTES) : "memory");
            asm volatile(
                "cp.async.bulk.shared::cta.global.mbarrier::complete_tx::bytes "
                "[%0], [%1], %2, [%3];"
                :: "r"(sp_a[k]), "l"(pred + base), "r"(TILE_BYTES), "r"(mbar_a[k])
                : "memory");
            asm volatile(
                "cp.async.bulk.shared::cta.global.mbarrier::complete_tx::bytes "
                "[%0], [%1], %2, [%3];"
                :: "r"(st_a[k]), "l"(tgt + base), "r"(TILE_BYTES), "r"(mbar_a[k])
                : "memory");
        }
    }
    __syncthreads();

    float axy = 0.f, awh = 0.f, aobj = 0.f, anoobj = 0.f, acls = 0.f;

    #pragma unroll
    for (int k = 0; k < 2; k++) {
        wait_parity0(mbar_a[k]);

        if (tid < CPB) {
            const float* p = smem + k * STAGE_FLOATS + tid * E;
            const float* g = smem + k * STAGE_FLOATS + TILE_FLOATS + tid * E;

            const float conf = g[4];
            const float m  = (conf > 0.0f)  ? 1.0f : 0.0f;
            const float nm = (conf == 0.0f) ? 1.0f : 0.0f;

            const float t0x = g[0], t0y = g[1], t0X = g[2], t0Y = g[3];
            const float a2 = (t0X - t0x) * (t0Y - t0y);

            float iou[2];
            #pragma unroll
            for (int b = 0; b < 2; b++) {
                const float* pb = p + b * 5;
                float ltx = fmaxf(pb[0], t0x);
                float lty = fmaxf(pb[1], t0y);
                float rbx = fminf(pb[2], t0X);
                float rby = fminf(pb[3], t0Y);
                float w = fmaxf(rbx - ltx, 0.0f);
                float h = fmaxf(rby - lty, 0.0f);
                float inter = w * h;
                float a1 = (pb[2] - pb[0]) * (pb[3] - pb[1]);
                iou[b] = inter / (a1 + a2 - inter);
            }

            // jnp.argmax takes the FIRST max on ties -> strict '>' for box 1
            const int best = (iou[1] > iou[0]) ? 1 : 0;
            const float maxiou = iou[best];

            const float* pb = p + best * 5;
            const float* tb = g + best * 5;

            const float dx = pb[0] - tb[0];
            const float dy = pb[1] - tb[1];
            axy += m * (dx * dx + dy * dy);

            const float dw = sqrtf(pb[2]) - sqrtf(tb[2]);
            const float dh = sqrtf(pb[3]) - sqrtf(tb[3]);
            awh += m * (dw * dw + dh * dh);

            const float dobj = pb[4] - maxiou;
            aobj += m * dobj * dobj;

            const float d4 = p[4] - g[4];
            const float d9 = p[9] - g[9];
            anoobj += nm * (d4 * d4 + d9 * d9);

            float cs = 0.0f;
            #pragma unroll
            for (int c = 10; c < 30; c++) {
                const float d = p[c] - g[c];
                cs += d * d;
            }
            acls += m * cs;
        }
    }

    // ---- Block reduction of 5 accumulated partials ----
    #pragma unroll
    for (int o = 16; o > 0; o >>= 1) {
        axy    += __shfl_down_sync(0xffffffffu, axy,    o);
        awh    += __shfl_down_sync(0xffffffffu, awh,    o);
        aobj   += __shfl_down_sync(0xffffffffu, aobj,   o);
        anoobj += __shfl_down_sync(0xffffffffu, anoobj, o);
        acls   += __shfl_down_sync(0xffffffffu, acls,   o);
    }
    const int wid  = tid >> 5;
    const int lane = tid & 31;
    if (lane == 0) {
        red[wid][0] = axy;
        red[wid][1] = awh;
        red[wid][2] = aobj;
        red[wid][3] = anoobj;
        red[wid][4] = acls;
    }
    __syncthreads();
    if (tid < 5) {
        float s = 0.0f;
        #pragma unroll
        for (int w = 0; w < THREADS / 32; w++) s += red[w][tid];
        atomicAdd(out + tid, s);
    }
}

extern "C" void kernel_launch(void* const* d_in, const int* in_sizes, int n_in,
                              void* d_out, int out_size) {
    const float* pred = (const float*)d_in[0];
    const float* tgt  = (const float*)d_in[1];
    float* out = (float*)d_out;

    cudaFuncSetAttribute(yolo_loss_kernel,
                         cudaFuncAttributeMaxDynamicSharedMemorySize, SMEM_DYN);
    cudaMemsetAsync(out, 0, (size_t)out_size * sizeof(float));
    yolo_loss_kernel<<<NBLK, THREADS, SMEM_DYN>>>(pred, tgt, out);
}

// round 12
// speedup vs baseline: 1.1103x; 1.0111x over previous
#include <cuda_runtime.h>
#include <cstdint>

// Problem constants
#define E           30                 // channels per cell (B*5 + C)
#define CELLS       802816             // 16384 * 7 * 7
#define CPB         64                 // cells per block
#define THREADS     64
#define TILE_FLOATS (CPB * E)          // 1920
#define TILE_BYTES  (TILE_FLOATS * 4)  // 7680 per tensor
#define NBLK        (CELLS / CPB)      // 12544

__device__ __forceinline__ uint32_t smem_u32(const void* p) {
    uint32_t a;
    asm("{ .reg .u64 t; cvta.to.shared.u64 t, %1; cvt.u32.u64 %0, t; }"
        : "=r"(a) : "l"(p));
    return a;
}

__global__ __launch_bounds__(THREADS)
void yolo_loss_kernel(const float* __restrict__ pred,
                      const float* __restrict__ tgt,
                      float* __restrict__ out) {
    __shared__ __align__(16) float sp[TILE_FLOATS];
    __shared__ __align__(16) float st[TILE_FLOATS];
    __shared__ __align__(8)  uint64_t mbar;
    __shared__ float red[THREADS / 32][5];

    const int tid = threadIdx.x;
    const long long base = (long long)blockIdx.x * TILE_FLOATS;

    const uint32_t mbar_a = smem_u32(&mbar);

    // tid 0: init barrier and immediately issue both TMA copies.
    // Other threads only touch the barrier after __syncthreads.
    if (tid == 0) {
        asm volatile("mbarrier.init.shared.b64 [%0], 1;"
                     :: "r"(mbar_a) : "memory");
        asm volatile("fence.proxy.async.shared::cta;" ::: "memory");
        asm volatile("mbarrier.arrive.expect_tx.shared.b64 _, [%0], %1;"
                     :: "r"(mbar_a), "r"(2 * TILE_BYTES) : "memory");
        asm volatile(
            "cp.async.bulk.shared::cta.global.mbarrier::complete_tx::bytes "
            "[%0], [%1], %2, [%3];"
            :: "r"(smem_u32(sp)), "l"(pred + base), "r"(TILE_BYTES), "r"(mbar_a)
            : "memory");
        asm volatile(
            "cp.async.bulk.shared::cta.global.mbarrier::complete_tx::bytes "
            "[%0], [%1], %2, [%3];"
            :: "r"(smem_u32(st)), "l"(tgt + base), "r"(TILE_BYTES), "r"(mbar_a)
            : "memory");
    }
    __syncthreads();

    // Wait for both TMA copies (phase parity 0).
    {
        uint32_t done;
        asm volatile(
            "{\n\t"
            ".reg .pred p;\n\t"
            "mbarrier.try_wait.parity.acquire.cta.shared::cta.b64 p, [%1], 0;\n\t"
            "selp.b32 %0, 1, 0, p;\n\t"
            "}"
            : "=r"(done) : "r"(mbar_a) : "memory");
        if (!done) {
            asm volatile(
                "{\n\t"
                ".reg .pred P1;\n\t"
                "WAIT_LOOP_%=:\n\t"
                "mbarrier.try_wait.parity.acquire.cta.shared::cta.b64 P1, [%0], 0, 0x989680;\n\t"
                "@P1 bra.uni WAIT_DONE_%=;\n\t"
                "bra.uni WAIT_LOOP_%=;\n\t"
                "WAIT_DONE_%=:\n\t"
                "}"
                :: "r"(mbar_a) : "memory");
        }
    }

    // ---- Per-thread cell compute (all 64 threads active) ----
    const float* p = sp + tid * E;
    const float* g = st + tid * E;

    const float conf = g[4];
    const float m  = (conf > 0.0f)  ? 1.0f : 0.0f;
    const float nm = (conf == 0.0f) ? 1.0f : 0.0f;

    const float t0x = g[0], t0y = g[1], t0X = g[2], t0Y = g[3];
    const float a2 = (t0X - t0x) * (t0Y - t0y);

    float iou[2];
    #pragma unroll
    for (int b = 0; b < 2; b++) {
        const float* pb = p + b * 5;
        float ltx = fmaxf(pb[0], t0x);
        float lty = fmaxf(pb[1], t0y);
        float rbx = fminf(pb[2], t0X);
        float rby = fminf(pb[3], t0Y);
        float w = fmaxf(rbx - ltx, 0.0f);
        float h = fmaxf(rby - lty, 0.0f);
        float inter = w * h;
        float a1 = (pb[2] - pb[0]) * (pb[3] - pb[1]);
        iou[b] = inter / (a1 + a2 - inter);
    }

    // jnp.argmax takes the FIRST max on ties -> strict '>' for box 1
    const int best = (iou[1] > iou[0]) ? 1 : 0;
    const float maxiou = iou[best];

    const float* pb = p + best * 5;
    const float* tb = g + best * 5;

    const float dx = pb[0] - tb[0];
    const float dy = pb[1] - tb[1];
    float lxy = m * (dx * dx + dy * dy);

    const float dw = sqrtf(pb[2]) - sqrtf(tb[2]);
    const float dh = sqrtf(pb[3]) - sqrtf(tb[3]);
    float lwh = m * (dw * dw + dh * dh);

    const float dobj = pb[4] - maxiou;
    float lobj = m * dobj * dobj;

    const float d4 = p[4] - g[4];
    const float d9 = p[9] - g[9];
    float lnoobj = nm * (d4 * d4 + d9 * d9);

    float cs = 0.0f;
    #pragma unroll
    for (int c = 10; c < 30; c++) {
        const float d = p[c] - g[c];
        cs += d * d;
    }
    float lcls = m * cs;

    // ---- Block reduction of 5 partials (2 warps) ----
    #pragma unroll
    for (int o = 16; o > 0; o >>= 1) {
        lxy    += __shfl_down_sync(0xffffffffu, lxy,    o);
        lwh    += __shfl_down_sync(0xffffffffu, lwh,    o);
        lobj   += __shfl_down_sync(0xffffffffu, lobj,   o);
        lnoobj += __shfl_down_sync(0xffffffffu, lnoobj, o);
        lcls   += __shfl_down_sync(0xffffffffu, lcls,   o);
    }
    const int wid  = tid >> 5;
    const int lane = tid & 31;
    if (lane == 0) {
        red[wid][0] = lxy;
        red[wid][1] = lwh;
        red[wid][2] = lobj;
        red[wid][3] = lnoobj;
        red[wid][4] = lcls;
    }
    __syncthreads();
    if (tid < 5) {
        float s = 0.0f;
        #pragma unroll
        for (int w = 0; w < THREADS / 32; w++) s += red[w][tid];
        atomicAdd(out + tid, s);
    }
}

extern "C" void kernel_launch(void* const* d_in, const int* in_sizes, int n_in,
                              void* d_out, int out_size) {
    const float* pred = (const float*)d_in[0];
    const float* tgt  = (const float*)d_in[1];
    float* out = (float*)d_out;

    cudaMemsetAsync(out, 0, (size_t)out_size * sizeof(float));
    yolo_loss_kernel<<<NBLK, THREADS>>>(pred, tgt, out);
}